// round 11
// baseline (speedup 1.0000x reference)
#include <cuda_runtime.h>
#include <cuda_fp16.h>
#include <math.h>
#include <stdint.h>

#define NN 10000
#define EE 100000
#define TBL 8192
#define TBL_RMAX 25.0f
#define WTAB_BLOCKS (TBL / 64)

// ---------------- scratch (device globals; no allocation allowed) ----------
__device__ float  g_h[NN * 128];       // MLP hidden (fp32)
__device__ __half g_phih[NN * 384];    // pass-1 node MLP output (fp16)
__device__ __half g_vh[NN * 384];      // input v as fp16 (pass-1 gathers)
__device__ float  g_vnew[NN * 384];    // v_new fp32
__device__ __half g_vnewh[NN * 384];   // v_new fp16 shadow (pass-2 gathers)
__device__ float  g_snew[NN * 128];    // s_new
__device__ __half g_s2h[NN * 384];     // pass-2 node MLP output (fp16)
__device__ __half g_wt[TBL * 384];     // filter weight lookup table over r (fp16)
__device__ float4 g_geo[EE];           // per-edge {unit.xyz, r} (CSR order)
__device__ int    g_deg[NN];           // zero-init at load; re-zeroed by k_pass2
__device__ int    g_ptr[NN + 1];
__device__ int    g_fill[NN];
__device__ int    g_csr_src[EE];

// ---------------- helpers ---------------------------------------------------
__device__ __forceinline__ float sspf(float x) {
    float sp = fmaxf(x, 0.0f) + log1pf(expf(-fabsf(x)));
    return sp - 0.69314718055994531f;
}
__device__ __forceinline__ float fcf(float u) {
    return (u < 5.0f) ? 0.5f * (__cosf(0.6283185307179586f * u) + 1.0f) : 0.0f;
}
__device__ __forceinline__ uint32_t f2tf32(float f) {
    uint32_t r;
    asm("cvt.rna.tf32.f32 %0, %1;" : "=r"(r) : "f"(f));
    return r;
}
__device__ __forceinline__ void mma_tf32(float c[4], const uint32_t a[4], const uint32_t b[2]) {
    asm volatile(
        "mma.sync.aligned.m16n8k8.row.col.f32.tf32.tf32.f32 "
        "{%0,%1,%2,%3},{%4,%5,%6,%7},{%8,%9},{%0,%1,%2,%3};"
        : "+f"(c[0]), "+f"(c[1]), "+f"(c[2]), "+f"(c[3])
        : "r"(a[0]), "r"(a[1]), "r"(a[2]), "r"(a[3]), "r"(b[0]), "r"(b[1]));
}

// ---------------- 256-thread GEMM tile: C[64,64] = act(A@W^T + b) -----------
template <int ACT, int HALF_OUT>
__device__ __forceinline__ void mlp_tile_256(const float* __restrict__ A,
                                             const float* __restrict__ W,
                                             const float* __restrict__ bias,
                                             void* __restrict__ Cv,
                                             int M, int NOUT, int bm, int bn,
                                             uint32_t* As, uint32_t* Ws) {
    int t = threadIdx.x;
    int warp = t >> 5, lane = t & 31;
    int gid = lane >> 2, tig = lane & 3;
    int wm = warp & 1, wn = warp >> 1;
    int m0 = bm * 64, n0 = bn * 64;

    float acc[2][2][4];
#pragma unroll
    for (int i = 0; i < 2; i++)
#pragma unroll
        for (int j = 0; j < 2; j++)
#pragma unroll
            for (int k = 0; k < 4; k++) acc[i][j][k] = 0.0f;

    for (int ks = 0; ks < 128; ks += 64) {
        __syncthreads();
        for (int i = t; i < 64 * 16; i += 256) {
            int row = i >> 4, c4 = (i & 15) << 2;
            float4 av = make_float4(0.f, 0.f, 0.f, 0.f);
            if (m0 + row < M)
                av = *(const float4*)(A + (size_t)(m0 + row) * 128 + ks + c4);
            uint32_t* da = &As[row * 68 + c4];
            da[0] = f2tf32(av.x); da[1] = f2tf32(av.y);
            da[2] = f2tf32(av.z); da[3] = f2tf32(av.w);
            float4 wv = *(const float4*)(W + (size_t)(n0 + row) * 128 + ks + c4);
            uint32_t* dw = &Ws[row * 68 + c4];
            dw[0] = f2tf32(wv.x); dw[1] = f2tf32(wv.y);
            dw[2] = f2tf32(wv.z); dw[3] = f2tf32(wv.w);
        }
        __syncthreads();
#pragma unroll
        for (int kc = 0; kc < 64; kc += 8) {
            uint32_t a[2][4], b[2][2];
#pragma unroll
            for (int ma = 0; ma < 2; ma++) {
                int r = wm * 32 + ma * 16 + gid;
                a[ma][0] = As[r * 68 + kc + tig];
                a[ma][1] = As[(r + 8) * 68 + kc + tig];
                a[ma][2] = As[r * 68 + kc + tig + 4];
                a[ma][3] = As[(r + 8) * 68 + kc + tig + 4];
            }
#pragma unroll
            for (int na = 0; na < 2; na++) {
                int cl = wn * 16 + na * 8 + gid;
                b[na][0] = Ws[cl * 68 + kc + tig];
                b[na][1] = Ws[cl * 68 + kc + tig + 4];
            }
#pragma unroll
            for (int ma = 0; ma < 2; ma++)
#pragma unroll
                for (int na = 0; na < 2; na++)
                    mma_tf32(acc[ma][na], a[ma], b[na]);
        }
    }
#pragma unroll
    for (int ma = 0; ma < 2; ma++) {
#pragma unroll
        for (int na = 0; na < 2; na++) {
            int m = m0 + wm * 32 + ma * 16 + gid;
            int n = n0 + wn * 16 + na * 8 + 2 * tig;
            float bx = bias[n], by = bias[n + 1];
            float o0 = acc[ma][na][0] + bx, o1 = acc[ma][na][1] + by;
            float o2 = acc[ma][na][2] + bx, o3 = acc[ma][na][3] + by;
            if (ACT) { o0 = sspf(o0); o1 = sspf(o1); o2 = sspf(o2); o3 = sspf(o3); }
            if (HALF_OUT) {
                __half* C = (__half*)Cv;
                if (m < M) *(__half2*)(C + (size_t)m * NOUT + n) = __floats2half2_rn(o0, o1);
                if (m + 8 < M) *(__half2*)(C + (size_t)(m + 8) * NOUT + n) = __floats2half2_rn(o2, o3);
            } else {
                float* C = (float*)Cv;
                if (m < M) *(float2*)(C + (size_t)m * NOUT + n) = make_float2(o0, o1);
                if (m + 8 < M) *(float2*)(C + (size_t)(m + 8) * NOUT + n) = make_float2(o2, o3);
            }
        }
    }
}

// ---------------- wtab tile (device fn; threads 0-127 do mma) ---------------
__device__ __forceinline__ void wtab_tile(const float* __restrict__ mvw,
                                          const float* __restrict__ mvb,
                                          int blk, uint32_t* As, uint32_t* Bs) {
    int t = threadIdx.x;
    int warp = t >> 5, lane = t & 31;
    int gid = lane >> 2, tig = lane & 3;
    int wm = warp & 1, wn = warp >> 1;
    int p0 = blk * 64;
    const float dR = TBL_RMAX / (float)TBL;

    for (int i = t; i < 64 * 20; i += 256) {
        int row = i / 20, n = i - row * 20 + 1;
        float r = fmaxf((float)(p0 + row) * dR, 1e-4f);
        float val = (0.6324555320336759f / r) * sinf(0.6283185307179586f * r * (float)n);
        As[row * 28 + (n - 1)] = f2tf32(val);
    }
    for (int i = t; i < 64 * 8; i += 256) {
        int row = i >> 3, c = 20 + (i & 7);
        As[row * 28 + c] = 0;
        Bs[row * 28 + c] = 0;
    }

    for (int n0 = 0; n0 < 384; n0 += 64) {
        __syncthreads();
        for (int i = t; i < 64 * 20; i += 256) {
            int row = i / 20, c = i - row * 20;
            Bs[row * 28 + c] = f2tf32(mvw[(size_t)(n0 + row) * 20 + c]);
        }
        __syncthreads();

        if (t < 128) {
            float acc[2][4][4];
#pragma unroll
            for (int i = 0; i < 2; i++)
#pragma unroll
                for (int j = 0; j < 4; j++)
#pragma unroll
                    for (int k = 0; k < 4; k++) acc[i][j][k] = 0.0f;

#pragma unroll
            for (int kc = 0; kc < 24; kc += 8) {
                uint32_t a[2][4], bb2[4][2];
#pragma unroll
                for (int ma = 0; ma < 2; ma++) {
                    int r = wm * 32 + ma * 16 + gid;
                    a[ma][0] = As[r * 28 + kc + tig];
                    a[ma][1] = As[(r + 8) * 28 + kc + tig];
                    a[ma][2] = As[r * 28 + kc + tig + 4];
                    a[ma][3] = As[(r + 8) * 28 + kc + tig + 4];
                }
#pragma unroll
                for (int na = 0; na < 4; na++) {
                    int cl = wn * 32 + na * 8 + gid;
                    bb2[na][0] = Bs[cl * 28 + kc + tig];
                    bb2[na][1] = Bs[cl * 28 + kc + tig + 4];
                }
#pragma unroll
                for (int ma = 0; ma < 2; ma++)
#pragma unroll
                    for (int na = 0; na < 4; na++)
                        mma_tf32(acc[ma][na], a[ma], bb2[na]);
            }

#pragma unroll
            for (int ma = 0; ma < 2; ma++) {
#pragma unroll
                for (int na = 0; na < 4; na++) {
                    int p = p0 + wm * 32 + ma * 16 + gid;
                    int n = n0 + wn * 32 + na * 8 + 2 * tig;
                    float bx = mvb[n], by = mvb[n + 1];
                    float o0 = fcf(acc[ma][na][0] + bx), o1 = fcf(acc[ma][na][1] + by);
                    float o2 = fcf(acc[ma][na][2] + bx), o3 = fcf(acc[ma][na][3] + by);
                    *(__half2*)(g_wt + (size_t)p * 384 + n) = __floats2half2_rn(o0, o1);
                    *(__half2*)(g_wt + (size_t)(p + 8) * 384 + n) = __floats2half2_rn(o2, o3);
                }
            }
        }
    }
}

// ---------------- megakernel A: wtab + hist + vhalf + pass1-MLP-layer1 ------
__global__ __launch_bounds__(256) void k_proA(const int* __restrict__ dst,
                                              const float* __restrict__ v,
                                              const float* __restrict__ mvw,
                                              const float* __restrict__ mvb,
                                              const float* __restrict__ s,
                                              const float* __restrict__ ms1w,
                                              const float* __restrict__ ms1b,
                                              float* __restrict__ h,
                                              int N, int E, int total,
                                              int histBlocks, int vBlocks) {
    __shared__ uint32_t sh[2 * 64 * 68];
    int b = blockIdx.x;
    int t = threadIdx.x;

    if (b < WTAB_BLOCKS) {
        wtab_tile(mvw, mvb, b, sh, sh + 64 * 28);
        return;
    }
    b -= WTAB_BLOCKS;
    if (b < histBlocks) {
        int e = b * 256 + t;
        if (e < E) atomicAdd(&g_deg[dst[e]], 1);
        return;
    }
    b -= histBlocks;
    if (b < vBlocks) {
        int i = (b * 256 + t) * 8;
        if (i < total) {
            float4 a = *(const float4*)(v + i);
            float4 c = *(const float4*)(v + i + 4);
            __half2 h0 = __floats2half2_rn(a.x, a.y);
            __half2 h1 = __floats2half2_rn(a.z, a.w);
            __half2 h2 = __floats2half2_rn(c.x, c.y);
            __half2 h3 = __floats2half2_rn(c.z, c.w);
            int4 o = make_int4(*(int*)&h0, *(int*)&h1, *(int*)&h2, *(int*)&h3);
            *(int4*)(g_vh + i) = o;
        }
        return;
    }
    b -= vBlocks;
    int bm = b >> 1, bn = b & 1;
    mlp_tile_256<1, 0>(s, ms1w, ms1b, h, N, 128, bm, bn, sh, sh + 64 * 68);
}

// ---------------- prefix scan ------------------------------------------------
__global__ void k_scan(int N) {
    __shared__ int wsum[32];
    __shared__ int carry_s;
    int t = threadIdx.x, lane = t & 31, wid = t >> 5;
    if (t == 0) carry_s = 0;
    __syncthreads();
    for (int base = 0; base < N; base += 1024) {
        int i = base + t;
        int v = (i < N) ? g_deg[i] : 0;
        int x = v;
#pragma unroll
        for (int o = 1; o < 32; o <<= 1) {
            int y = __shfl_up_sync(0xFFFFFFFFu, x, o);
            if (lane >= o) x += y;
        }
        if (lane == 31) wsum[wid] = x;
        __syncthreads();
        if (wid == 0) {
            int w = wsum[lane];
#pragma unroll
            for (int o = 1; o < 32; o <<= 1) {
                int y = __shfl_up_sync(0xFFFFFFFFu, w, o);
                if (lane >= o) w += y;
            }
            wsum[lane] = w;
        }
        __syncthreads();
        int excl = x - v + (wid ? wsum[wid - 1] : 0) + carry_s;
        if (i < N) {
            g_ptr[i] = excl;
            g_fill[i] = excl;
        }
        int total = wsum[31];
        __syncthreads();
        if (t == 0) carry_s += total;
        __syncthreads();
    }
    if (threadIdx.x == 0) g_ptr[N] = carry_s;
}

// ---------------- megakernel C: fill_edge + pass1-MLP-layer2 ----------------
__global__ __launch_bounds__(256) void k_proC(const float* __restrict__ x,
                                              const int* __restrict__ src,
                                              const int* __restrict__ dst,
                                              const float* __restrict__ h,
                                              const float* __restrict__ ms2w,
                                              const float* __restrict__ ms2b,
                                              __half* __restrict__ phih,
                                              int N, int E, int fillBlocks) {
    __shared__ uint32_t sh[2 * 64 * 68];
    int b = blockIdx.x;
    int t = threadIdx.x;

    if (b < fillBlocks) {
        int e = b * 256 + t;
        if (e >= E) return;
        int d = dst[e];
        int sn = src[e];
        float xs0 = x[sn * 3 + 0], xs1 = x[sn * 3 + 1], xs2 = x[sn * 3 + 2];
        float xd0 = x[d * 3 + 0],  xd1 = x[d * 3 + 1],  xd2 = x[d * 3 + 2];
        int pos = atomicAdd(&g_fill[d], 1);
        g_csr_src[pos] = sn;
        float vx = xs0 - xd0;
        float vy = xs1 - xd1;
        float vz = xs2 - xd2;
        float r = sqrtf(vx * vx + vy * vy + vz * vz + 1e-5f);
        float inv = 1.0f / r;
        g_geo[pos] = make_float4(vx * inv, vy * inv, vz * inv, r);
        return;
    }
    b -= fillBlocks;
    int bm = b / 6, bn = b - bm * 6;
    mlp_tile_256<0, 1>(h, ms2w, ms2b, phih, N, 384, bm, bn, sh, sh + 64 * 68);
}

// ---------------- standalone GEMM (pass-2 MLP layers) ------------------------
template <int ACT, int HALF_OUT>
__global__ __launch_bounds__(256) void k_gemm(const float* __restrict__ A,
                                              const float* __restrict__ W,
                                              const float* __restrict__ bias,
                                              void* __restrict__ Cv,
                                              int M, int NOUT, int nTiles) {
    __shared__ uint32_t sh[2 * 64 * 68];
    int b = blockIdx.x;
    int bm = b / nTiles, bn = b - bm * nTiles;
    mlp_tile_256<ACT, HALF_OUT>(A, W, bias, Cv, M, NOUT, bm, bn, sh, sh + 64 * 68);
}

// ---------------- pass 1 consumer: 2 warps per node (64 features each) ------
__global__ __launch_bounds__(256) void k_pass1(const float* __restrict__ v,
                                               const float* __restrict__ s, int N) {
    int gw = (blockIdx.x * blockDim.x + threadIdx.x) >> 5;
    int node = gw >> 1;
    int halfid = gw & 1;
    int lane = threadIdx.x & 31;
    if (node >= N) return;
    int f0 = halfid * 64 + lane * 2;           // 2 features per lane
    int beg = g_ptr[node], end = g_ptr[node + 1];

    float dv[6];
    float ds2x = 0.0f, ds2y = 0.0f;
#pragma unroll
    for (int k = 0; k < 6; k++) dv[k] = 0.0f;

    const float invDR = (float)TBL / TBL_RMAX;

#pragma unroll 2
    for (int p = beg; p < end; p++) {
        int sn = g_csr_src[p];
        float4 geo = g_geo[p];
        float rt = fminf(geo.w * invDR, (float)TBL - 1.001f);
        int i0 = (int)rt;
        __half2 fr2 = __float2half2_rn(rt - (float)i0);

        const __half* ph = g_phih + (size_t)sn * 384 + f0;
        __half2 pv = *(const __half2*)(ph);
        __half2 ps = *(const __half2*)(ph + 128);
        __half2 pr = *(const __half2*)(ph + 256);

        const __half* wl = g_wt + (size_t)i0 * 384 + f0;
        __half2 wvl = *(const __half2*)(wl);
        __half2 wsl = *(const __half2*)(wl + 128);
        __half2 wrl = *(const __half2*)(wl + 256);
        __half2 wvh = *(const __half2*)(wl + 384);
        __half2 wsh = *(const __half2*)(wl + 512);
        __half2 wrh = *(const __half2*)(wl + 640);

        __half2 wv = __hfma2(__hsub2(wvh, wvl), fr2, wvl);
        __half2 ws = __hfma2(__hsub2(wsh, wsl), fr2, wsl);
        __half2 wr = __hfma2(__hsub2(wrh, wrl), fr2, wrl);

        float2 vv  = __half22float2(__hmul2(pv, wv));
        float2 dsq = __half22float2(__hmul2(ps, ws));
        float2 rr  = __half22float2(__hmul2(pr, wr));
        ds2x += dsq.x; ds2y += dsq.y;

        const __half* vr = g_vh + (size_t)sn * 384 + 3 * f0;
        int q0 = *(const int*)(vr);
        int q1 = *(const int*)(vr + 2);
        int q2 = *(const int*)(vr + 4);
        float2 a0 = __half22float2(*(__half2*)&q0);  // (x0, y0)
        float2 a1 = __half22float2(*(__half2*)&q1);  // (z0, x1)
        float2 a2 = __half22float2(*(__half2*)&q2);  // (y1, z1)

        dv[0] += a0.x * vv.x + rr.x * geo.x;
        dv[1] += a0.y * vv.x + rr.x * geo.y;
        dv[2] += a1.x * vv.x + rr.x * geo.z;
        dv[3] += a1.y * vv.y + rr.y * geo.x;
        dv[4] += a2.x * vv.y + rr.y * geo.y;
        dv[5] += a2.y * vv.y + rr.y * geo.z;
    }

    // own-node combine
    const float* vi = v + (size_t)node * 384 + 3 * f0;
    float2 b0 = *(const float2*)(vi);
    float2 b1 = *(const float2*)(vi + 2);
    float2 b2 = *(const float2*)(vi + 4);
    b0.x += dv[0]; b0.y += dv[1];
    b1.x += dv[2]; b1.y += dv[3];
    b2.x += dv[4]; b2.y += dv[5];
    float* vo = g_vnew + (size_t)node * 384 + 3 * f0;
    *(float2*)(vo) = b0; *(float2*)(vo + 2) = b1; *(float2*)(vo + 4) = b2;

    {
        __half2 h0 = __floats2half2_rn(b0.x, b0.y);
        __half2 h1 = __floats2half2_rn(b1.x, b1.y);
        __half2 h2 = __floats2half2_rn(b2.x, b2.y);
        __half* vh2 = g_vnewh + (size_t)node * 384 + 3 * f0;
        *(int*)(vh2)     = *(int*)&h0;
        *(int*)(vh2 + 2) = *(int*)&h1;
        *(int*)(vh2 + 4) = *(int*)&h2;
    }

    float2 sv = *(const float2*)(s + (size_t)node * 128 + f0);
    sv.x += ds2x; sv.y += ds2y;
    *(float2*)(g_snew + (size_t)node * 128 + f0) = sv;
}

// ---------------- pass 2 consumer: 2 warps per node (+ g_deg re-zero) -------
__global__ __launch_bounds__(256) void k_pass2(float* __restrict__ out, int N) {
    int gw = (blockIdx.x * blockDim.x + threadIdx.x) >> 5;
    int node = gw >> 1;
    int halfid = gw & 1;
    int lane = threadIdx.x & 31;
    if (node >= N) return;
    int f0 = halfid * 64 + lane * 2;
    int beg = g_ptr[node], end = g_ptr[node + 1];
    int deg = end - beg;
    if (halfid == 0 && lane == 0) g_deg[node] = 0;

    float uv[6];
    float mv0 = 0.f, mv1 = 0.f, sv0 = 0.f, sv1 = 0.f, zz0 = 0.f, zz1 = 0.f;
#pragma unroll
    for (int k = 0; k < 6; k++) uv[k] = 0.0f;

#pragma unroll 2
    for (int p = beg; p < end; p++) {
        int sn = g_csr_src[p];
        const __half* vr = g_vnewh + (size_t)sn * 384 + 3 * f0;
        int q0 = *(const int*)(vr);
        int q1 = *(const int*)(vr + 2);
        int q2 = *(const int*)(vr + 4);
        float2 a0 = __half22float2(*(__half2*)&q0);
        float2 a1 = __half22float2(*(__half2*)&q1);
        float2 a2 = __half22float2(*(__half2*)&q2);
        uv[0] += a0.x; uv[1] += a0.y; uv[2] += a1.x;
        uv[3] += a1.y; uv[4] += a2.x; uv[5] += a2.y;

        const __half* sr = g_s2h + (size_t)sn * 384 + f0;
        float2 m = __half22float2(*(const __half2*)(sr));
        float2 ss = __half22float2(*(const __half2*)(sr + 128));
        float2 z = __half22float2(*(const __half2*)(sr + 256));
        mv0 += m.x; mv1 += m.y;
        sv0 += ss.x; sv1 += ss.y;
        zz0 += z.x; zz1 += z.y;
    }
    float inv = 1.0f / fmaxf((float)deg, 1.0f);
#pragma unroll
    for (int k = 0; k < 6; k++) uv[k] *= inv;
    float avv0 = mv0 * inv, avv1 = mv1 * inv;
    float asv0 = sv0 * inv, asv1 = sv1 * inv;
    float ass0 = zz0 * inv, ass1 = zz1 * inv;

    const float* vi = g_vnew + (size_t)node * 384 + 3 * f0;
    float2 b0 = *(const float2*)(vi);
    float2 b1 = *(const float2*)(vi + 2);
    float2 b2 = *(const float2*)(vi + 4);
    b0.x += uv[0] * avv0; b0.y += uv[1] * avv0; b1.x += uv[2] * avv0;
    b1.y += uv[3] * avv1; b2.x += uv[4] * avv1; b2.y += uv[5] * avv1;
    float* vo = out + (size_t)node * 384 + 3 * f0;
    *(float2*)(vo) = b0; *(float2*)(vo + 2) = b1; *(float2*)(vo + 4) = b2;

    float2 sn2 = *(const float2*)(g_snew + (size_t)node * 128 + f0);
    float ssq0 = uv[0] * uv[0] + uv[1] * uv[1] + uv[2] * uv[2];
    float ssq1 = uv[3] * uv[3] + uv[4] * uv[4] + uv[5] * uv[5];
    sn2.x += (ssq0 / (ssq0 + 1e-5f)) * asv0 + ass0;
    sn2.y += (ssq1 / (ssq1 + 1e-5f)) * asv1 + ass1;
    *(float2*)(out + (size_t)N * 384 + (size_t)node * 128 + f0) = sn2;
}

// ---------------- launcher --------------------------------------------------
extern "C" void kernel_launch(void* const* d_in, const int* in_sizes, int n_in,
                              void* d_out, int out_size) {
    const float* x     = (const float*)d_in[0];
    const float* v     = (const float*)d_in[1];
    const float* s     = (const float*)d_in[2];
    const float* ms1_w = (const float*)d_in[3];
    const float* ms1_b = (const float*)d_in[4];
    const float* ms2_w = (const float*)d_in[5];
    const float* ms2_b = (const float*)d_in[6];
    const float* mv_w  = (const float*)d_in[7];
    const float* mv_b  = (const float*)d_in[8];
    const float* us1_w = (const float*)d_in[9];
    const float* us1_b = (const float*)d_in[10];
    const float* us2_w = (const float*)d_in[11];
    const float* us2_b = (const float*)d_in[12];
    const int*   src   = (const int*)d_in[13];
    const int*   dst   = (const int*)d_in[14];
    float* out = (float*)d_out;

    int N = in_sizes[0] / 3;
    int E = in_sizes[13];

    float *p_h, *p_snew;
    __half *p_phih, *p_s2h;
    cudaGetSymbolAddress((void**)&p_h, g_h);
    cudaGetSymbolAddress((void**)&p_phih, g_phih);
    cudaGetSymbolAddress((void**)&p_snew, g_snew);
    cudaGetSymbolAddress((void**)&p_s2h, g_s2h);

    int mTiles = (N + 63) / 64;
    int histBlocks = (E + 255) / 256;
    int vBlocks = (N * 384 / 8 + 255) / 256;
    int fillBlocks = (E + 255) / 256;

    // megakernel A: wtab + histogram + v->fp16 + pass-1 MLP layer 1
    k_proA<<<WTAB_BLOCKS + histBlocks + vBlocks + mTiles * 2, 256>>>(
        dst, v, mv_w, mv_b, s, ms1_w, ms1_b, p_h, N, E, N * 384, histBlocks, vBlocks);

    k_scan<<<1, 1024>>>(N);

    // megakernel C: fill_edge + pass-1 MLP layer 2
    k_proC<<<fillBlocks + mTiles * 6, 256>>>(
        x, src, dst, p_h, ms2_w, ms2_b, p_phih, N, E, fillBlocks);

    // pass-1 reduce (2 warps per node)
    k_pass1<<<(N * 64 + 255) / 256, 256>>>(v, s, N);

    // pass-2 node MLP on s_new
    k_gemm<1, 0><<<mTiles * 2, 256>>>(p_snew, us1_w, us1_b, p_h, N, 128, 2);
    k_gemm<0, 1><<<mTiles * 6, 256>>>(p_h, us2_w, us2_b, p_s2h, N, 384, 6);

    // pass-2 reduce + final combine (2 warps per node, + deg re-zero)
    k_pass2<<<(N * 64 + 255) / 256, 256>>>(out, N);
}